// round 5
// baseline (speedup 1.0000x reference)
#include <cuda_runtime.h>

#define B_VOX   256
#define NPC     40
#define NE      32
#define LPC     16                   // lanes per compartment (2 orders/lane = 32 orders)
#define CPW     2                    // compartments per warp
#define WARPS   (NPC / CPW)          // 20
#define THREADS (WARPS * 32)         // 640

typedef unsigned long long ull;

// packed f32x2 helpers (ptxas never auto-fuses these from C++)
__device__ __forceinline__ ull f2pk(float lo, float hi) {
    ull r; asm("mov.b64 %0, {%1, %2};" : "=l"(r) : "f"(lo), "f"(hi)); return r;
}
__device__ __forceinline__ void f2unpk(ull v, float& lo, float& hi) {
    asm("mov.b64 {%0, %1}, %2;" : "=f"(lo), "=f"(hi) : "l"(v));
}
__device__ __forceinline__ ull mul2(ull a, ull b) {
    ull r; asm("mul.rn.f32x2 %0, %1, %2;" : "=l"(r) : "l"(a), "l"(b)); return r;
}
__device__ __forceinline__ ull fma2(ull a, ull b, ull c) {
    ull r; asm("fma.rn.f32x2 %0, %1, %2, %3;" : "=l"(r) : "l"(a), "l"(b), "l"(c)); return r;
}

// EPG step x' = S·(D·T·D)·S·x (D commutes with S). Order o = 2*s + j + 1,
// sub-lane s = lane&15, j = 0..1; compartment = wz*2 + (lane>>4).
// Packed over the (j=0, j=1) order pair (shared coefficients):
//   t  =  C·Z ;  tn = -C·Z
//   mF =  A·sF + B·sG + t
//   mG =  B·sF + A·sG + tn
//   mZ =  Dz·sG - Dz·sF + Ez·Z
// shift1: sF[o]=F[o-1] (sF[1]=x0), sG[o]=G[o+1] (sG[32]=0), mx0=e2²·G[1]
// shift2: F[o]=mF[o-1] (F[1]=mx0), G[o]=mG[o+1] (G[32]=0),  echo=mG[1]

__global__ __launch_bounds__(THREADS) void epg_kernel(
    const float* __restrict__ refoc,    // (256,)
    const float* __restrict__ t2s,      // (256, 40)
    const float* __restrict__ wts,      // (256, 40)
    float* __restrict__ out)            // (256, 32)
{
    const int b    = blockIdx.x;
    const int lane = threadIdx.x & 31;
    const int wz   = threadIdx.x >> 5;
    const int s    = lane & (LPC - 1);
    const int grp  = lane >> 4;
    const bool sLo = (s == 0);
    const bool sHi = (s == LPC - 1);
    const unsigned FULL = 0xFFFFFFFFu;

    __shared__ float smem[NPC][NE + 1];      // +1 pad: conflict-free leader STS

    // per-voxel rotation constants
    const float a  = refoc[b] * 0.017453292519943295f;
    const float ah = 0.5f * a;
    const float sa = sinf(a),  ca = cosf(a);
    const float sh = sinf(ah), ch = cosf(ah);
    const float c2 = ch * ch,  s2 = sh * sh;
    const float e1   = 0.99501247919268231f;     // exp(-5/1000)
    const float e1sq = e1 * e1;

    // per-compartment fused coefficients, broadcast-packed
    const int   c    = wz * CPW + grp;
    const float e2   = expf(-5.0f / t2s[b * NPC + c]);
    const float e2sq = e2 * e2;
    const float A    = c2 * e2sq;
    const float Bc   = s2 * e2sq;
    const float Cc   = sa * e2 * e1;
    const float Dz   = 0.5f * sa * e1 * e2;
    const float Ez   = ca * e1sq;
    const float w    = wts[b * NPC + c];

    const ull A2  = f2pk(A,   A);
    const ull B2  = f2pk(Bc,  Bc);
    const ull C2  = f2pk(Cc,  Cc);
    const ull Cn2 = f2pk(-Cc, -Cc);
    const ull D2  = f2pk(Dz,  Dz);
    const ull Dn2 = f2pk(-Dz, -Dz);
    const ull E2  = f2pk(Ez,  Ez);

    // initial state: x0 = sin(ah); G(order 1) = cos(ah)
    float F0 = 0.f, F1 = 0.f;
    float G0 = sLo ? ch : 0.f, G1 = 0.f;
    ull   Z2 = f2pk(0.f, 0.f);
    float x0 = sh;                               // meaningful on sub-lane 0

    #pragma unroll
    for (int k = 0; k < NE; ++k) {
        // ---- shift 1: only boundary elements cross lanes (width-16 groups) ----
        const float fc = __shfl_up_sync  (FULL, F1, 1, LPC);
        const float gc = __shfl_down_sync(FULL, G0, 1, LPC);
        const float mx0 = e2sq * G0;             // sub-lane 0: order-1 G pre-shift

        const float sF0 = sLo ? x0 : fc;
        const float sF1 = F0;
        const float sG0 = G1;
        const float sG1 = sHi ? 0.f : gc;

        // ---- fused rotation+decay, packed over the order pair ----
        const ull sF2 = f2pk(sF0, sF1);
        const ull sG2 = f2pk(sG0, sG1);
        const ull t2p = mul2(C2,  Z2);
        const ull tn2 = mul2(Cn2, Z2);
        const ull mF2 = fma2(A2, sF2, fma2(B2, sG2, t2p));
        const ull mG2 = fma2(B2, sF2, fma2(A2, sG2, tn2));
        const ull mZ2 = fma2(D2, sG2, fma2(Dn2, sF2, mul2(E2, Z2)));

        float mF0, mF1, mG0, mG1;
        f2unpk(mF2, mF0, mF1);
        f2unpk(mG2, mG0, mG1);

        // ---- shift 2 ----
        const float fc2 = __shfl_up_sync  (FULL, mF1, 1, LPC);
        const float gc2 = __shfl_down_sync(FULL, mG0, 1, LPC);
        F0 = sLo ? mx0 : fc2;
        F1 = mF0;
        G0 = mG1;
        G1 = sHi ? 0.f : gc2;
        Z2 = mZ2;
        x0 = mG0;                                // new x0 (= echo on sub-lane 0)

        if (sLo) smem[c][k] = w * mG0;           // weighted echo, 1 predicated STS
    }

    __syncthreads();

    // warp 0: sum 40 compartments per echo, normalize by echo 0
    if (threadIdx.x < 32) {
        float acc = 0.0f;
        #pragma unroll
        for (int r = 0; r < NPC; ++r) acc += smem[r][lane];
        const float acc0 = __shfl_sync(FULL, acc, 0);
        out[b * NE + lane] = acc / acc0;
    }
}

extern "C" void kernel_launch(void* const* d_in, const int* in_sizes, int n_in,
                              void* d_out, int out_size) {
    const float* refoc = (const float*)d_in[0];
    const float* t2s   = (const float*)d_in[1];
    const float* wts   = (const float*)d_in[2];
    float* out = (float*)d_out;
    epg_kernel<<<B_VOX, THREADS>>>(refoc, t2s, wts, out);
}

// round 6
// speedup vs baseline: 1.1505x; 1.1505x over previous
#include <cuda_runtime.h>

#define B_VOX   256
#define NPC     40
#define NE      32
#define ORD     4                    // EPG orders per lane
#define LPC     8                    // lanes per compartment (32 orders)
#define CPW     4                    // compartments per warp
#define WARPS   (NPC / CPW)          // 10
#define THREADS (WARPS * 32)         // 320

// y-form EPG: y_{k+1} = S^2 · M · y_k  (y = S·x, E = S·M·S, M = D·T·D blockdiag)
// lane s (=lane&7) holds orders 4s+1..4s+4 as F[4],G[4],Z[4]; x0 on sub-lane 0.
// M per order:  t = C·Z;  mF = A·F + B·G + t;  mG = B·F + A·G - t
//               mZ = Ez·Z + Dz·(G - F);        mx0 = e2²·x0
// S² (shift F down-2 / G up-2 in order space):
//   F[0] <- lane s-1 mF[2]   (lane0: mG[0] = mG_1)
//   F[1] <- lane s-1 mF[3]   (lane0: mx0)
//   F[2] <- mF[0];  F[3] <- mF[1]
//   G[0] <- mG[2];  G[1] <- mG[3]
//   G[2] <- lane s+1 mG[0]   (lane7: 0)
//   G[3] <- lane s+1 mG[1]   (lane7: 0)
//   x0   <- mG[1] (lane0);   echo_k = lane0 mG[0]
// Init y0 = S·x0: x0 = cos(a/2), F_1 = sin(a/2), rest 0.

__global__ __launch_bounds__(THREADS) void epg_kernel(
    const float* __restrict__ refoc,    // (256,)
    const float* __restrict__ t2s,      // (256, 40)
    const float* __restrict__ wts,      // (256, 40)
    float* __restrict__ out)            // (256, 32)
{
    const int b    = blockIdx.x;
    const int lane = threadIdx.x & 31;
    const int wz   = threadIdx.x >> 5;
    const int s    = lane & (LPC - 1);
    const int grp  = lane >> 3;
    const bool sLo = (s == 0);
    const bool sHi = (s == LPC - 1);
    const unsigned FULL = 0xFFFFFFFFu;

    __shared__ float smem[NPC][NE + 1];      // +1 pad: conflict-free leader STS

    // per-voxel rotation constants
    const float a  = refoc[b] * 0.017453292519943295f;
    const float ah = 0.5f * a;
    const float sa = sinf(a),  ca = cosf(a);
    const float sh = sinf(ah), ch = cosf(ah);
    const float c2 = ch * ch,  s2 = sh * sh;
    const float e1   = 0.99501247919268231f;     // exp(-5/1000)
    const float e1sq = e1 * e1;

    // per-compartment fused coefficients
    const int   c    = wz * CPW + grp;
    const float e2   = expf(-5.0f / t2s[b * NPC + c]);
    const float e2sq = e2 * e2;
    const float A    = c2 * e2sq;
    const float Bc   = s2 * e2sq;
    const float Cc   = sa * e2 * e1;
    const float Dz   = 0.5f * sa * e1 * e2;
    const float Ez   = ca * e1sq;
    const float w    = wts[b * NPC + c];

    // init y0 = S·x0
    float F[ORD] = {sLo ? sh : 0.f, 0.f, 0.f, 0.f};
    float G[ORD] = {0.f, 0.f, 0.f, 0.f};
    float Z[ORD] = {0.f, 0.f, 0.f, 0.f};
    float x0 = ch;                               // meaningful on sub-lane 0

    #pragma unroll 4
    for (int k = 0; k < NE; ++k) {
        // ---- M = D·T·D (all local) ----
        float mF[ORD], mG[ORD], mZ[ORD];
        #pragma unroll
        for (int j = 0; j < ORD; ++j) {
            const float t = Cc * Z[j];
            mF[j] = fmaf(A,  F[j], fmaf(Bc, G[j],  t));
            mG[j] = fmaf(Bc, F[j], fmaf(A,  G[j], -t));
            mZ[j] = fmaf(Ez, Z[j], Dz * (G[j] - F[j]));
        }
        const float mx0 = e2sq * x0;

        // ---- S²: single shuffle segment ----
        const float cF0 = __shfl_up_sync  (FULL, mF[2], 1, LPC);
        const float cF1 = __shfl_up_sync  (FULL, mF[3], 1, LPC);
        const float cG0 = __shfl_down_sync(FULL, mG[0], 1, LPC);
        const float cG1 = __shfl_down_sync(FULL, mG[1], 1, LPC);

        if (sLo) smem[c][k] = w * mG[0];         // echo_k (lane-0 local)

        F[0] = sLo ? mG[0] : cF0;
        F[1] = sLo ? mx0   : cF1;
        F[2] = mF[0];
        F[3] = mF[1];
        G[0] = mG[2];
        G[1] = mG[3];
        G[2] = sHi ? 0.f : cG0;
        G[3] = sHi ? 0.f : cG1;
        Z[0] = mZ[0]; Z[1] = mZ[1]; Z[2] = mZ[2]; Z[3] = mZ[3];
        x0   = mG[1];                            // new x0 (valid on sub-lane 0)
    }

    __syncthreads();

    // warp 0: sum 40 compartments per echo, normalize by echo 0
    if (threadIdx.x < 32) {
        float acc = 0.0f;
        #pragma unroll
        for (int r = 0; r < NPC; ++r) acc += smem[r][lane];
        const float acc0 = __shfl_sync(FULL, acc, 0);
        out[b * NE + lane] = acc / acc0;
    }
}

extern "C" void kernel_launch(void* const* d_in, const int* in_sizes, int n_in,
                              void* d_out, int out_size) {
    const float* refoc = (const float*)d_in[0];
    const float* t2s   = (const float*)d_in[1];
    const float* wts   = (const float*)d_in[2];
    float* out = (float*)d_out;
    epg_kernel<<<B_VOX, THREADS>>>(refoc, t2s, wts, out);
}

// round 7
// speedup vs baseline: 1.1801x; 1.0257x over previous
#include <cuda_runtime.h>

#define B_VOX   256
#define NPC     40
#define NE      32
#define LPC     16                   // lanes per compartment, 2 orders/lane
#define CPW     2                    // compartments per warp
#define WARPS   (NPC / CPW)          // 20
#define THREADS (WARPS * 32)         // 640

// y-form EPG: y_{k+1} = S^2 · M · y_k  (y = S·x, E = S·M·S, M = D·T·D blockdiag)
// lane s (=lane&15) holds orders 2s+1, 2s+2 as (F0,F1,G0,G1,u0,u1); x0 on s=0.
// u = C·Z substitution:
//   mF = A·F + B·G + u
//   mG = B·F + A·G - u
//   u' = CD·G - CD·F + Ez·u        (CD = C·Dz)
//   mx0 = e2²·x0
// S² (2-order shift = one full lane at ORD=2):
//   F[0] <- prev-lane mF[0]   (lane0: own mG[0])
//   F[1] <- prev-lane mF[1]   (lane0: mx0)
//   G[0] <- next-lane mG[0]   (lane15: 0)
//   G[1] <- next-lane mG[1]   (lane15: 0)
//   x0   <- mG[1] (lane0);  echo_k = lane0 mG[0]
// Init y0 = S·x0: x0 = cos(a/2), F_1 = sin(a/2), rest 0.

__global__ __launch_bounds__(THREADS) void epg_kernel(
    const float* __restrict__ refoc,    // (256,)
    const float* __restrict__ t2s,      // (256, 40)
    const float* __restrict__ wts,      // (256, 40)
    float* __restrict__ out)            // (256, 32)
{
    const int b    = blockIdx.x;
    const int lane = threadIdx.x & 31;
    const int wz   = threadIdx.x >> 5;
    const int s    = lane & (LPC - 1);
    const int grp  = lane >> 4;
    const bool sLo = (s == 0);
    const bool sHi = (s == LPC - 1);
    const unsigned FULL = 0xFFFFFFFFu;

    __shared__ float smem[NPC][NE + 1];      // +1 pad: conflict-free leader STS

    // per-voxel rotation constants
    const float a  = refoc[b] * 0.017453292519943295f;
    const float ah = 0.5f * a;
    const float sa = sinf(a),  ca = cosf(a);
    const float sh = sinf(ah), ch = cosf(ah);
    const float c2 = ch * ch,  s2 = sh * sh;
    const float e1   = 0.99501247919268231f;     // exp(-5/1000)
    const float e1sq = e1 * e1;

    // per-compartment fused coefficients
    const int   c    = wz * CPW + grp;
    const float e2   = expf(-5.0f / t2s[b * NPC + c]);
    const float e2sq = e2 * e2;
    const float A    = c2 * e2sq;
    const float Bc   = s2 * e2sq;
    const float Cc   = sa * e2 * e1;
    const float Dz   = 0.5f * sa * e1 * e2;
    const float Ez   = ca * e1sq;
    const float CD   = Cc * Dz;                  // C·Dz for the u-recurrence
    const float w    = wts[b * NPC + c];

    // init y0 = S·x0
    float F0 = sLo ? sh : 0.f, F1 = 0.f;
    float G0 = 0.f,            G1 = 0.f;
    float u0 = 0.f,            u1 = 0.f;
    float x0 = ch;                               // meaningful on sub-lane 0

    #pragma unroll
    for (int k = 0; k < NE; ++k) {
        // ---- M = D·T·D (all local), u = C·Z form ----
        const float mF0 = fmaf(A,  F0, fmaf(Bc, G0,  u0));
        const float mG0 = fmaf(Bc, F0, fmaf(A,  G0, -u0));
        const float nu0 = fmaf(CD, G0, fmaf(-CD, F0, Ez * u0));
        const float mF1 = fmaf(A,  F1, fmaf(Bc, G1,  u1));
        const float mG1 = fmaf(Bc, F1, fmaf(A,  G1, -u1));
        const float nu1 = fmaf(CD, G1, fmaf(-CD, F1, Ez * u1));
        const float mx0 = e2sq * x0;

        // ---- S²: one shuffle segment (full-lane shift) ----
        const float cF0 = __shfl_up_sync  (FULL, mF0, 1, LPC);
        const float cF1 = __shfl_up_sync  (FULL, mF1, 1, LPC);
        const float cG0 = __shfl_down_sync(FULL, mG0, 1, LPC);
        const float cG1 = __shfl_down_sync(FULL, mG1, 1, LPC);

        if (sLo) smem[c][k] = w * mG0;           // echo_k (lane-0 local)

        F0 = sLo ? mG0 : cF0;
        F1 = sLo ? mx0 : cF1;
        G0 = sHi ? 0.f : cG0;
        G1 = sHi ? 0.f : cG1;
        u0 = nu0;
        u1 = nu1;
        x0 = mG1;                                // new x0 (valid on sub-lane 0)
    }

    __syncthreads();

    // warp 0: sum 40 compartments per echo, normalize by echo 0
    if (threadIdx.x < 32) {
        float acc = 0.0f;
        #pragma unroll
        for (int r = 0; r < NPC; ++r) acc += smem[r][lane];
        const float acc0 = __shfl_sync(FULL, acc, 0);
        out[b * NE + lane] = acc / acc0;
    }
}

extern "C" void kernel_launch(void* const* d_in, const int* in_sizes, int n_in,
                              void* d_out, int out_size) {
    const float* refoc = (const float*)d_in[0];
    const float* t2s   = (const float*)d_in[1];
    const float* wts   = (const float*)d_in[2];
    float* out = (float*)d_out;
    epg_kernel<<<B_VOX, THREADS>>>(refoc, t2s, wts, out);
}